// round 3
// baseline (speedup 1.0000x reference)
#include <cuda_runtime.h>
#include <cuda.h>
#include <cuda_fp16.h>
#include <cstdint>

// ============================================================
// Problem sizes
// ============================================================
#define B_DIM 8192
#define K_DIM 4096
#define N_DIM 4096

// GEMM tiling
#define BM 128
#define BN 256
#define BK 32                  // fp16 elements per K-chunk (64 bytes per row)
#define NST 4                  // pipeline stages
#define KITERS (K_DIM / BK)    // 128

// Padded smem row: 32 halfs = 16 words of data, padded to 20 words (80B).
// 20*r mod 32 for r=0..7 -> {0,20,8,28,16,4,24,12}: disjoint 4-word groups
// => conflict-free b32 fragment loads at any word offset 0..15.
#define ROW_W 20
#define A_STAGE_W (BM * ROW_W)             // 2560 words = 10240 B
#define B_STAGE_W (BN * ROW_W)             // 5120 words = 20480 B
#define STAGE_W   (A_STAGE_W + B_STAGE_W)  // 7680 words = 30720 B

#define SM_BIAS_W   0                      // BN floats = 256 words
#define SM_STAGE0_W 256
#define SMEM_BYTES  ((SM_STAGE0_W + NST * STAGE_W) * 4)   // 123,904 B

// ============================================================
// Device-global scratch (no allocations allowed)
// ============================================================
__device__ __half g_Ah[(size_t)B_DIM * K_DIM];   // 64 MB  x as fp16
__device__ __half g_Bt[(size_t)N_DIM * K_DIM];   // 32 MB  sign(W)^T, K-major

// ============================================================
// Small asm helpers
// ============================================================
__device__ __forceinline__ uint32_t smem_u32(const void* p) {
    uint32_t a;
    asm("{ .reg .u64 t; cvta.to.shared.u64 t, %1; cvt.u32.u64 %0, t; }" : "=r"(a) : "l"(p));
    return a;
}

__device__ __forceinline__ void cp_async16(uint32_t saddr, const void* gaddr) {
    asm volatile("cp.async.cg.shared.global [%0], [%1], 16;" :: "r"(saddr), "l"(gaddr));
}
#define CP_COMMIT() asm volatile("cp.async.commit_group;" ::: "memory")
template <int N>
__device__ __forceinline__ void cp_wait() {
    asm volatile("cp.async.wait_group %0;" :: "n"(N) : "memory");
}

__device__ __forceinline__ void mma16816(float& d0, float& d1, float& d2, float& d3,
                                         uint32_t a0, uint32_t a1, uint32_t a2, uint32_t a3,
                                         uint32_t b0, uint32_t b1) {
    asm volatile(
        "mma.sync.aligned.m16n8k16.row.col.f32.f16.f16.f32 "
        "{%0,%1,%2,%3}, {%4,%5,%6,%7}, {%8,%9}, {%0,%1,%2,%3};"
        : "+f"(d0), "+f"(d1), "+f"(d2), "+f"(d3)
        : "r"(a0), "r"(a1), "r"(a2), "r"(a3), "r"(b0), "r"(b1));
}

// ============================================================
// Prep 1: x fp32 -> fp16
// ============================================================
__global__ void __launch_bounds__(256)
prep_x_kernel(const float4* __restrict__ x, uint2* __restrict__ xh, int n4) {
    int i = blockIdx.x * blockDim.x + threadIdx.x;
    if (i >= n4) return;
    float4 v = x[i];
    __half2 lo = __floats2half2_rn(v.x, v.y);
    __half2 hi = __floats2half2_rn(v.z, v.w);
    uint2 o;
    o.x = *reinterpret_cast<uint32_t*>(&lo);
    o.y = *reinterpret_cast<uint32_t*>(&hi);
    xh[i] = o;
}

// ============================================================
// Prep 2: Bt[n][k] = sign(W[k][n]) as fp16 (tiled transpose)
// ============================================================
__global__ void __launch_bounds__(256)
prep_bt_kernel(const float* __restrict__ w, __half* __restrict__ bt) {
    __shared__ float tile[32][33];
    const int n_base = blockIdx.x * 32;
    const int k_base = blockIdx.y * 32;
#pragma unroll
    for (int i = 0; i < 32; i += 8) {
        tile[threadIdx.y + i][threadIdx.x] =
            w[(size_t)(k_base + threadIdx.y + i) * N_DIM + n_base + threadIdx.x];
    }
    __syncthreads();
#pragma unroll
    for (int i = 0; i < 32; i += 8) {
        float v = tile[threadIdx.x][threadIdx.y + i];
        float s = (v > 0.f) ? 1.f : ((v < 0.f) ? -1.f : 0.f);
        bt[(size_t)(n_base + threadIdx.y + i) * K_DIM + k_base + threadIdx.x] = __float2half_rn(s);
    }
}

// ============================================================
// Main GEMM: out[BM,BN] = Ah @ Bt^T + bias
// 256 threads = 8 warps (2 x 4); warp tile 64x64; mma m16n8k16 fp16->fp32
// ============================================================
__global__ void __launch_bounds__(256, 1)
binary_dense_gemm(const __half* __restrict__ Ah,
                  const __half* __restrict__ Bt,
                  const float* __restrict__ bias,
                  float* __restrict__ out) {
    extern __shared__ char smem_raw[];
    uint32_t* smw = reinterpret_cast<uint32_t*>(smem_raw);
    float* bias_sm = reinterpret_cast<float*>(smem_raw);
    const uint32_t sb = smem_u32(smem_raw);

    const int tid = threadIdx.x;
    const int wid = tid >> 5;
    const int lid = tid & 31;
    const int wm = wid >> 2;        // 0..1 : warp m-row (64 rows each)
    const int wn = wid & 3;         // 0..3 : warp n-col (64 cols each)
    const int r  = lid >> 2;        // 0..7
    const int c2 = lid & 3;         // 0..3

    // ---- tile rasterization: supergroups of 8 m-tiles x 16 n-tiles ----
    const int bid = blockIdx.x;
    const int gid = bid >> 7;            // / (8*16)
    const int rem = bid & 127;
    const int mt  = gid * 8 + (rem & 7);
    const int nt  = rem >> 3;
    const int m0  = mt * BM;
    const int n0  = nt * BN;

    // ---- bias to smem ----
    bias_sm[tid] = bias[n0 + tid];       // 256 threads x 1 = BN

    // ---- per-thread cp.async slots: 2 A chunks + 4 B chunks ----
    // chunk = 16B = 8 halfs. A: 128 rows x 4 chunks; B: 256 rows x 4 chunks.
    int a_row[2], a_ch[2], b_row[4], b_ch[4];
#pragma unroll
    for (int i = 0; i < 2; i++) { int c = tid + i * 256; a_row[i] = c >> 2; a_ch[i] = c & 3; }
#pragma unroll
    for (int i = 0; i < 4; i++) { int c = tid + i * 256; b_row[i] = c >> 2; b_ch[i] = c & 3; }

    const __half* gA = Ah + (size_t)m0 * K_DIM;
    const __half* gB = Bt + (size_t)n0 * K_DIM;

    // smem byte offsets (stage-relative), constant per thread
    uint32_t sA_off[2], sB_off[4];
#pragma unroll
    for (int i = 0; i < 2; i++) sA_off[i] = a_row[i] * (ROW_W * 4) + a_ch[i] * 16;
#pragma unroll
    for (int i = 0; i < 4; i++) sB_off[i] = (A_STAGE_W * 4) + b_row[i] * (ROW_W * 4) + b_ch[i] * 16;

    auto issue_stage = [&](int s, int kt) {
        const uint32_t st = sb + (SM_STAGE0_W + s * STAGE_W) * 4;
        const int k0 = kt * BK;
#pragma unroll
        for (int i = 0; i < 2; i++)
            cp_async16(st + sA_off[i], gA + (size_t)a_row[i] * K_DIM + k0 + a_ch[i] * 8);
#pragma unroll
        for (int i = 0; i < 4; i++)
            cp_async16(st + sB_off[i], gB + (size_t)b_row[i] * K_DIM + k0 + b_ch[i] * 8);
    };

    // ---- prologue: fill NST-1 stages ----
#pragma unroll
    for (int s = 0; s < NST - 1; s++) { issue_stage(s, s); CP_COMMIT(); }

    // ---- accumulators: 4 m-subtiles x 8 n-subtiles x 4 regs ----
    float acc[4][8][4];
#pragma unroll
    for (int i = 0; i < 4; i++)
#pragma unroll
        for (int j = 0; j < 8; j++)
#pragma unroll
            for (int q = 0; q < 4; q++) acc[i][j][q] = 0.f;

    // warp-local smem word bases
    const int aw_base = SM_STAGE0_W + (wm * 64) * ROW_W;               // + stage offset
    const int bw_base = SM_STAGE0_W + A_STAGE_W + (wn * 64) * ROW_W;

    for (int kt = 0; kt < KITERS; kt++) {
        cp_wait<NST - 2>();
        __syncthreads();

        // prefetch next stage into the just-freed buffer
        if (kt + NST - 1 < KITERS) issue_stage((kt + NST - 1) & (NST - 1), kt + NST - 1);
        CP_COMMIT();

        const int st_w = (kt & (NST - 1)) * STAGE_W;
        const uint32_t* __restrict__ swA = smw + st_w + aw_base;
        const uint32_t* __restrict__ swB = smw + st_w + bw_base;

#pragma unroll
        for (int w = 0; w < 2; w++) {          // two k16 steps per BK=32
            const int wb = w * 8;              // word offset within row

            // B fragments: 8 n-subtiles x 2 regs
            uint32_t bf[8][2];
#pragma unroll
            for (int j = 0; j < 8; j++) {
                const int rowB = j * 8 + r;
                bf[j][0] = swB[rowB * ROW_W + wb + c2];
                bf[j][1] = swB[rowB * ROW_W + wb + c2 + 4];
            }
            // A fragments: 4 m-subtiles x 4 regs
            uint32_t af[4][4];
#pragma unroll
            for (int i = 0; i < 4; i++) {
                const int rowA = i * 16 + r;
                af[i][0] = swA[rowA * ROW_W + wb + c2];
                af[i][1] = swA[(rowA + 8) * ROW_W + wb + c2];
                af[i][2] = swA[rowA * ROW_W + wb + c2 + 4];
                af[i][3] = swA[(rowA + 8) * ROW_W + wb + c2 + 4];
            }
#pragma unroll
            for (int i = 0; i < 4; i++)
#pragma unroll
                for (int j = 0; j < 8; j++)
                    mma16816(acc[i][j][0], acc[i][j][1], acc[i][j][2], acc[i][j][3],
                             af[i][0], af[i][1], af[i][2], af[i][3],
                             bf[j][0], bf[j][1]);
        }
        __syncthreads();
    }

    // ---- epilogue: C frag (r, 2*c2) / (r+8, 2*c2) pairs + bias ----
#pragma unroll
    for (int i = 0; i < 4; i++) {
        const int row = m0 + wm * 64 + i * 16 + r;
        float* o0 = out + (size_t)row * N_DIM + n0;
        float* o1 = out + (size_t)(row + 8) * N_DIM + n0;
#pragma unroll
        for (int j = 0; j < 8; j++) {
            const int col = wn * 64 + j * 8 + c2 * 2;
            const float b0 = bias_sm[col], b1 = bias_sm[col + 1];
            float2 v0 = make_float2(acc[i][j][0] + b0, acc[i][j][1] + b1);
            float2 v1 = make_float2(acc[i][j][2] + b0, acc[i][j][3] + b1);
            *reinterpret_cast<float2*>(o0 + col) = v0;
            *reinterpret_cast<float2*>(o1 + col) = v1;
        }
    }
}

// ============================================================
// Host side
// ============================================================
extern "C" void kernel_launch(void* const* d_in, const int* in_sizes, int n_in,
                              void* d_out, int out_size) {
    const float* x    = (const float*)d_in[0];
    const float* w    = (const float*)d_in[1];
    const float* bias = (const float*)d_in[2];
    float* out        = (float*)d_out;

    void *p_ah = nullptr, *p_bt = nullptr;
    cudaGetSymbolAddress(&p_ah, g_Ah);
    cudaGetSymbolAddress(&p_bt, g_Bt);

    // Prep
    const int n4 = (B_DIM * K_DIM) / 4;
    prep_x_kernel<<<(n4 + 255) / 256, 256>>>((const float4*)x, (uint2*)p_ah, n4);
    prep_bt_kernel<<<dim3(N_DIM / 32, K_DIM / 32), dim3(32, 8)>>>(w, (__half*)p_bt);

    // GEMM
    static bool attr_set = false;
    if (!attr_set) {
        cudaFuncSetAttribute(binary_dense_gemm,
                             cudaFuncAttributeMaxDynamicSharedMemorySize, SMEM_BYTES);
        attr_set = true;
    }
    const int grid = (B_DIM / BM) * (N_DIM / BN);   // 64 * 16 = 1024
    binary_dense_gemm<<<grid, 256, SMEM_BYTES>>>(
        (const __half*)p_ah, (const __half*)p_bt, bias, out);
}

// round 4
// speedup vs baseline: 1.4148x; 1.4148x over previous
#include <cuda_runtime.h>
#include <cuda.h>
#include <cuda_fp16.h>
#include <cstdint>

// ============================================================
// Problem sizes
// ============================================================
#define B_DIM 8192
#define K_DIM 4096
#define N_DIM 4096

// GEMM tiling
#define BM 128
#define BN 256
#define BK 64                  // halfs per K-chunk = 128 bytes/row (SW128 swizzle)
#define NST 3
#define KITERS (K_DIM / BK)    // 64

#define A_STAGE_BYTES (BM * 128)                       // 16384
#define B_STAGE_BYTES (BN * 128)                       // 32768
#define STAGE_BYTES   (A_STAGE_BYTES + B_STAGE_BYTES)  // 49152

#define SM_ST0      1024                               // bias occupies [0,1024)
#define SMEM_BYTES  (SM_ST0 + NST * STAGE_BYTES)       // 148480

// ============================================================
// Device-global scratch
// ============================================================
__device__ __half g_Ah[(size_t)B_DIM * K_DIM];   // 64 MB  x as fp16
__device__ __half g_Bt[(size_t)N_DIM * K_DIM];   // 32 MB  sign(W)^T, K-major

// ============================================================
// Asm helpers
// ============================================================
__device__ __forceinline__ uint32_t smem_u32(const void* p) {
    uint32_t a;
    asm("{ .reg .u64 t; cvta.to.shared.u64 t, %1; cvt.u32.u64 %0, t; }" : "=r"(a) : "l"(p));
    return a;
}

__device__ __forceinline__ void cp_async16(uint32_t saddr, const void* gaddr) {
    asm volatile("cp.async.cg.shared.global [%0], [%1], 16;" :: "r"(saddr), "l"(gaddr));
}
#define CP_COMMIT() asm volatile("cp.async.commit_group;" ::: "memory")
template <int N>
__device__ __forceinline__ void cp_wait() {
    asm volatile("cp.async.wait_group %0;" :: "n"(N) : "memory");
}

#define LDSM_X4(d, addr) \
    asm volatile("ldmatrix.sync.aligned.m8n8.x4.shared.b16 {%0,%1,%2,%3}, [%4];" \
        : "=r"((d)[0]), "=r"((d)[1]), "=r"((d)[2]), "=r"((d)[3]) : "r"(addr))

__device__ __forceinline__ void mma16816(float* d,
                                         const uint32_t* a, uint32_t b0, uint32_t b1) {
    asm volatile(
        "mma.sync.aligned.m16n8k16.row.col.f32.f16.f16.f32 "
        "{%0,%1,%2,%3}, {%4,%5,%6,%7}, {%8,%9}, {%0,%1,%2,%3};"
        : "+f"(d[0]), "+f"(d[1]), "+f"(d[2]), "+f"(d[3])
        : "r"(a[0]), "r"(a[1]), "r"(a[2]), "r"(a[3]), "r"(b0), "r"(b1));
}

// ============================================================
// Prep 1: x fp32 -> fp16
// ============================================================
__global__ void __launch_bounds__(256)
prep_x_kernel(const float4* __restrict__ x, uint2* __restrict__ xh, int n4) {
    int i = blockIdx.x * blockDim.x + threadIdx.x;
    if (i >= n4) return;
    float4 v = x[i];
    __half2 lo = __floats2half2_rn(v.x, v.y);
    __half2 hi = __floats2half2_rn(v.z, v.w);
    uint2 o;
    o.x = *reinterpret_cast<uint32_t*>(&lo);
    o.y = *reinterpret_cast<uint32_t*>(&hi);
    xh[i] = o;
}

// ============================================================
// Prep 2: Bt[n][k] = sign(W[k][n]) as fp16 (tiled transpose)
// ============================================================
__global__ void __launch_bounds__(256)
prep_bt_kernel(const float* __restrict__ w, __half* __restrict__ bt) {
    __shared__ float tile[32][33];
    const int n_base = blockIdx.x * 32;
    const int k_base = blockIdx.y * 32;
#pragma unroll
    for (int i = 0; i < 32; i += 8) {
        tile[threadIdx.y + i][threadIdx.x] =
            w[(size_t)(k_base + threadIdx.y + i) * N_DIM + n_base + threadIdx.x];
    }
    __syncthreads();
#pragma unroll
    for (int i = 0; i < 32; i += 8) {
        float v = tile[threadIdx.x][threadIdx.y + i];
        float s = (v > 0.f) ? 1.f : ((v < 0.f) ? -1.f : 0.f);
        bt[(size_t)(n_base + threadIdx.y + i) * K_DIM + k_base + threadIdx.x] = __float2half_rn(s);
    }
}

// ============================================================
// Main GEMM: 256 threads = 8 warps (2x4), warp tile 64x64
// BK=64, swizzled 128B rows, ldmatrix.x4 fragment loads
// ============================================================
__global__ void __launch_bounds__(256, 1)
binary_dense_gemm(const __half* __restrict__ Ah,
                  const __half* __restrict__ Bt,
                  const float* __restrict__ bias,
                  float* __restrict__ out) {
    extern __shared__ char smem_raw[];
    float* bias_sm = reinterpret_cast<float*>(smem_raw);
    const uint32_t sb = smem_u32(smem_raw);

    const int tid = threadIdx.x;
    const int wid = tid >> 5;
    const int lid = tid & 31;
    const int wm = wid >> 2;        // 0..1
    const int wn = wid & 3;         // 0..3

    // ---- tile rasterization: supergroups of 8 m-tiles x 16 n-tiles ----
    const int bid = blockIdx.x;
    const int gid = bid >> 7;
    const int rem = bid & 127;
    const int mt  = gid * 8 + (rem & 7);
    const int nt  = rem >> 3;
    const int m0  = mt * BM;
    const int n0  = nt * BN;

    bias_sm[tid] = bias[n0 + tid];

    // ---- cp.async mapping: A 4 chunks, B 8 chunks per thread ----
    // chunk = 16B; row has 8 chunks (128B). Swizzle: chunk' = chunk ^ (row&7).
    uint32_t aOff[4]; int aGI[4];
#pragma unroll
    for (int i = 0; i < 4; i++) {
        int c = tid + i * 256, r = c >> 3, ch = c & 7;
        aOff[i] = r * 128 + ((ch ^ (r & 7)) << 4);
        aGI[i]  = r * K_DIM + ch * 8;
    }
    uint32_t bOff[8]; int bGI[8];
#pragma unroll
    for (int i = 0; i < 8; i++) {
        int c = tid + i * 256, r = c >> 3, ch = c & 7;
        bOff[i] = r * 128 + ((ch ^ (r & 7)) << 4);
        bGI[i]  = r * K_DIM + ch * 8;
    }

    const __half* gA = Ah + (size_t)m0 * K_DIM;
    const __half* gB = Bt + (size_t)n0 * K_DIM;

    auto issue_stage = [&](int slot, int kt) {
        const uint32_t st = sb + SM_ST0 + slot * STAGE_BYTES;
        const int k0 = kt * BK;
#pragma unroll
        for (int i = 0; i < 4; i++) cp_async16(st + aOff[i], gA + aGI[i] + k0);
#pragma unroll
        for (int i = 0; i < 8; i++) cp_async16(st + A_STAGE_BYTES + bOff[i], gB + bGI[i] + k0);
    };

    // ---- prologue ----
    issue_stage(0, 0); CP_COMMIT();
    issue_stage(1, 1); CP_COMMIT();

    // ---- ldmatrix lane addressing ----
    // A x4: lanes 0-15 -> rows base+(lid&15) chunk lo; lanes 16-31 -> chunk hi
    const int hbA = lid >> 4;
    uint32_t aRowByte[4], aR7[4];
#pragma unroll
    for (int i = 0; i < 4; i++) {
        int r = wm * 64 + i * 16 + (lid & 15);
        aRowByte[i] = r * 128;
        aR7[i] = r & 7;
    }
    // B x4 (two n8 subtiles): row = base + ((lid>>4)<<3) + (lid&7); hi-chunk bit = (lid>>3)&1
    const int hbB = (lid >> 3) & 1;
    uint32_t bRowByte[4], bR7[4];
#pragma unroll
    for (int j = 0; j < 4; j++) {
        int r = wn * 64 + j * 16 + ((lid >> 4) << 3) + (lid & 7);
        bRowByte[j] = r * 128;
        bR7[j] = r & 7;
    }

    float acc[4][8][4];
#pragma unroll
    for (int i = 0; i < 4; i++)
#pragma unroll
        for (int j = 0; j < 8; j++)
#pragma unroll
            for (int q = 0; q < 4; q++) acc[i][j][q] = 0.f;

    int sc = 0, si = 2;
    for (int kt = 0; kt < KITERS; kt++) {
        cp_wait<1>();
        __syncthreads();

        const int nk = kt + 2;
        if (nk < KITERS) issue_stage(si, nk);
        CP_COMMIT();

        const uint32_t stA = sb + SM_ST0 + sc * STAGE_BYTES;
        const uint32_t stB = stA + A_STAGE_BYTES;

#pragma unroll
        for (int w = 0; w < 4; w++) {          // four k16 steps per BK=64
            uint32_t af[4][4];
#pragma unroll
            for (int i = 0; i < 4; i++) {
                uint32_t addr = stA + aRowByte[i] + ((uint32_t)((2 * w + hbA) ^ aR7[i]) << 4);
                LDSM_X4(af[i], addr);
            }
            uint32_t bf[4][4];
#pragma unroll
            for (int j = 0; j < 4; j++) {
                uint32_t addr = stB + bRowByte[j] + ((uint32_t)((2 * w + hbB) ^ bR7[j]) << 4);
                LDSM_X4(bf[j], addr);
            }
#pragma unroll
            for (int i = 0; i < 4; i++)
#pragma unroll
                for (int j = 0; j < 4; j++) {
                    mma16816(acc[i][2 * j],     af[i], bf[j][0], bf[j][1]);
                    mma16816(acc[i][2 * j + 1], af[i], bf[j][2], bf[j][3]);
                }
        }

        sc = (sc == NST - 1) ? 0 : sc + 1;
        si = (si == NST - 1) ? 0 : si + 1;
    }

    // ---- epilogue ----
    const int r4 = lid >> 2, c4 = lid & 3;
#pragma unroll
    for (int i = 0; i < 4; i++) {
        const int row = m0 + wm * 64 + i * 16 + r4;
        float* o0 = out + (size_t)row * N_DIM + n0;
        float* o1 = out + (size_t)(row + 8) * N_DIM + n0;
#pragma unroll
        for (int j = 0; j < 8; j++) {
            const int col = wn * 64 + j * 8 + c4 * 2;
            const float b0 = bias_sm[col], b1 = bias_sm[col + 1];
            float2 v0 = make_float2(acc[i][j][0] + b0, acc[i][j][1] + b1);
            float2 v1 = make_float2(acc[i][j][2] + b0, acc[i][j][3] + b1);
            *reinterpret_cast<float2*>(o0 + col) = v0;
            *reinterpret_cast<float2*>(o1 + col) = v1;
        }
    }
}

// ============================================================
// Host side
// ============================================================
extern "C" void kernel_launch(void* const* d_in, const int* in_sizes, int n_in,
                              void* d_out, int out_size) {
    const float* x    = (const float*)d_in[0];
    const float* w    = (const float*)d_in[1];
    const float* bias = (const float*)d_in[2];
    float* out        = (float*)d_out;

    void *p_ah = nullptr, *p_bt = nullptr;
    cudaGetSymbolAddress(&p_ah, g_Ah);
    cudaGetSymbolAddress(&p_bt, g_Bt);

    const int n4 = (B_DIM * K_DIM) / 4;
    prep_x_kernel<<<(n4 + 255) / 256, 256>>>((const float4*)x, (uint2*)p_ah, n4);
    prep_bt_kernel<<<dim3(N_DIM / 32, K_DIM / 32), dim3(32, 8)>>>(w, (__half*)p_bt);

    static bool attr_set = false;
    if (!attr_set) {
        cudaFuncSetAttribute(binary_dense_gemm,
                             cudaFuncAttributeMaxDynamicSharedMemorySize, SMEM_BYTES);
        attr_set = true;
    }
    const int grid = (B_DIM / BM) * (N_DIM / BN);   // 1024
    binary_dense_gemm<<<grid, 256, SMEM_BYTES>>>(
        (const __half*)p_ah, (const __half*)p_bt, bias, out);
}

// round 5
// speedup vs baseline: 1.7084x; 1.2075x over previous
#include <cuda_runtime.h>
#include <cuda.h>
#include <cuda_fp16.h>
#include <cstdint>

// ============================================================
// Problem sizes
// ============================================================
#define B_DIM 8192
#define K_DIM 4096
#define N_DIM 4096

// GEMM tiling
#define BM 128
#define BN 256
#define BK 64                  // halfs per K-chunk = 128 bytes/row (swizzled)
#define NST 3
#define KITERS (K_DIM / BK)    // 64

#define A_STAGE_BYTES (BM * 128)                       // 16384
#define B_STAGE_BYTES (BN * 128)                       // 32768
#define STAGE_BYTES   (A_STAGE_BYTES + B_STAGE_BYTES)  // 49152

#define SM_ST0      1024                               // bias occupies [0,1024)
#define SMEM_BYTES  (SM_ST0 + NST * STAGE_BYTES)       // 148480

// ============================================================
// Device-global scratch
// ============================================================
__device__ __half g_Ah[(size_t)B_DIM * K_DIM];   // 64 MB  x as fp16
__device__ __half g_Bt[(size_t)N_DIM * K_DIM];   // 32 MB  sign(W)^T, K-major

// ============================================================
// Asm helpers
// ============================================================
__device__ __forceinline__ uint32_t smem_u32(const void* p) {
    uint32_t a;
    asm("{ .reg .u64 t; cvta.to.shared.u64 t, %1; cvt.u32.u64 %0, t; }" : "=r"(a) : "l"(p));
    return a;
}

__device__ __forceinline__ void cp_async16(uint32_t saddr, const void* gaddr) {
    asm volatile("cp.async.cg.shared.global [%0], [%1], 16;" :: "r"(saddr), "l"(gaddr));
}
#define CP_COMMIT() asm volatile("cp.async.commit_group;" ::: "memory")
template <int N>
__device__ __forceinline__ void cp_wait() {
    asm volatile("cp.async.wait_group %0;" :: "n"(N) : "memory");
}

#define LDSM_X4(d, addr) \
    asm volatile("ldmatrix.sync.aligned.m8n8.x4.shared.b16 {%0,%1,%2,%3}, [%4];" \
        : "=r"((d)[0]), "=r"((d)[1]), "=r"((d)[2]), "=r"((d)[3]) : "r"(addr))

__device__ __forceinline__ void mma16816(float* d,
                                         const uint32_t* a, uint32_t b0, uint32_t b1) {
    asm volatile(
        "mma.sync.aligned.m16n8k16.row.col.f32.f16.f16.f32 "
        "{%0,%1,%2,%3}, {%4,%5,%6,%7}, {%8,%9}, {%0,%1,%2,%3};"
        : "+f"(d[0]), "+f"(d[1]), "+f"(d[2]), "+f"(d[3])
        : "r"(a[0]), "r"(a[1]), "r"(a[2]), "r"(a[3]), "r"(b0), "r"(b1));
}

// ============================================================
// Prep 1: x fp32 -> fp16
// ============================================================
__global__ void __launch_bounds__(256)
prep_x_kernel(const float4* __restrict__ x, uint2* __restrict__ xh, int n4) {
    int i = blockIdx.x * blockDim.x + threadIdx.x;
    if (i >= n4) return;
    float4 v = x[i];
    __half2 lo = __floats2half2_rn(v.x, v.y);
    __half2 hi = __floats2half2_rn(v.z, v.w);
    uint2 o;
    o.x = *reinterpret_cast<uint32_t*>(&lo);
    o.y = *reinterpret_cast<uint32_t*>(&hi);
    xh[i] = o;
}

// ============================================================
// Prep 2: Bt[n][k] = sign(W[k][n]) as fp16 (tiled transpose)
// ============================================================
__global__ void __launch_bounds__(256)
prep_bt_kernel(const float* __restrict__ w, __half* __restrict__ bt) {
    __shared__ float tile[32][33];
    const int n_base = blockIdx.x * 32;
    const int k_base = blockIdx.y * 32;
#pragma unroll
    for (int i = 0; i < 32; i += 8) {
        tile[threadIdx.y + i][threadIdx.x] =
            w[(size_t)(k_base + threadIdx.y + i) * N_DIM + n_base + threadIdx.x];
    }
    __syncthreads();
#pragma unroll
    for (int i = 0; i < 32; i += 8) {
        float v = tile[threadIdx.x][threadIdx.y + i];
        float s = (v > 0.f) ? 1.f : ((v < 0.f) ? -1.f : 0.f);
        bt[(size_t)(n_base + threadIdx.y + i) * K_DIM + k_base + threadIdx.x] = __float2half_rn(s);
    }
}

// ============================================================
// Main GEMM: 256 threads = 8 warps (2x4), warp tile 64x64
// BK=64, swizzled 128B rows, ldmatrix.x4, register-double-buffered fragments
// ============================================================
__global__ void __launch_bounds__(256, 1)
binary_dense_gemm(const __half* __restrict__ Ah,
                  const __half* __restrict__ Bt,
                  const float* __restrict__ bias,
                  float* __restrict__ out) {
    extern __shared__ char smem_raw[];
    float* bias_sm = reinterpret_cast<float*>(smem_raw);
    const uint32_t sb = smem_u32(smem_raw);

    const int tid = threadIdx.x;
    const int wid = tid >> 5;
    const int lid = tid & 31;
    const int wm = wid >> 2;        // 0..1
    const int wn = wid & 3;         // 0..3

    // ---- tile rasterization: supergroups of 8 m-tiles x 16 n-tiles ----
    const int bid = blockIdx.x;
    const int gid = bid >> 7;
    const int rem = bid & 127;
    const int mt  = gid * 8 + (rem & 7);
    const int nt  = rem >> 3;
    const int m0  = mt * BM;
    const int n0  = nt * BN;

    bias_sm[tid] = bias[n0 + tid];

    // ---- cp.async mapping: A 4 chunks, B 8 chunks per thread ----
    uint32_t aOff[4]; int aGI[4];
#pragma unroll
    for (int i = 0; i < 4; i++) {
        int c = tid + i * 256, r = c >> 3, ch = c & 7;
        aOff[i] = r * 128 + ((ch ^ (r & 7)) << 4);
        aGI[i]  = r * K_DIM + ch * 8;
    }
    uint32_t bOff[8]; int bGI[8];
#pragma unroll
    for (int i = 0; i < 8; i++) {
        int c = tid + i * 256, r = c >> 3, ch = c & 7;
        bOff[i] = r * 128 + ((ch ^ (r & 7)) << 4);
        bGI[i]  = r * K_DIM + ch * 8;
    }

    const __half* gA = Ah + (size_t)m0 * K_DIM;
    const __half* gB = Bt + (size_t)n0 * K_DIM;

    auto issue_stage = [&](int slot, int kt) {
        const uint32_t st = sb + SM_ST0 + slot * STAGE_BYTES;
        const int k0 = kt * BK;
#pragma unroll
        for (int i = 0; i < 4; i++) cp_async16(st + aOff[i], gA + aGI[i] + k0);
#pragma unroll
        for (int i = 0; i < 8; i++) cp_async16(st + A_STAGE_BYTES + bOff[i], gB + bGI[i] + k0);
    };

    // ---- ldmatrix lane addressing ----
    const int hbA = lid >> 4;
    uint32_t aRowByte[4], aR7[4];
#pragma unroll
    for (int i = 0; i < 4; i++) {
        int r = wm * 64 + i * 16 + (lid & 15);
        aRowByte[i] = r * 128;
        aR7[i] = r & 7;
    }
    const int hbB = (lid >> 3) & 1;
    uint32_t bRowByte[4], bR7[4];
#pragma unroll
    for (int j = 0; j < 4; j++) {
        int r = wn * 64 + j * 16 + ((lid >> 4) << 3) + (lid & 7);
        bRowByte[j] = r * 128;
        bR7[j] = r & 7;
    }

    // ---- prologue: fill 2 of 3 stages ----
    issue_stage(0, 0); CP_COMMIT();
    issue_stage(1, 1); CP_COMMIT();

    float acc[4][8][4];
#pragma unroll
    for (int i = 0; i < 4; i++)
#pragma unroll
        for (int j = 0; j < 8; j++)
#pragma unroll
            for (int q = 0; q < 4; q++) acc[i][j][q] = 0.f;

    // fragment double buffers
    uint32_t af[2][4][4], bf[2][4][4];

    // wait for stage 0, load w=0 fragments into buffer 0
    cp_wait<1>();
    __syncthreads();
    {
        const uint32_t stA = sb + SM_ST0;
        const uint32_t stB = stA + A_STAGE_BYTES;
#pragma unroll
        for (int i = 0; i < 4; i++)
            LDSM_X4(af[0][i], stA + aRowByte[i] + ((uint32_t)(hbA ^ aR7[i]) << 4));
#pragma unroll
        for (int j = 0; j < 4; j++)
            LDSM_X4(bf[0][j], stB + bRowByte[j] + ((uint32_t)(hbB ^ bR7[j]) << 4));
    }

    int sc = 0;          // stage being consumed
    int si = 2;          // slot to fill this iteration
    for (int kt = 0; kt < KITERS; kt++) {
        // issue stage kt+2 into the slot freed at kt-1 (ordered by the w3-sync)
        const int nk = kt + 2;
        if (nk < KITERS) issue_stage(si, nk);
        CP_COMMIT();

        const uint32_t stA = sb + SM_ST0 + sc * STAGE_BYTES;
        const uint32_t stB = stA + A_STAGE_BYTES;
        const int sn = (sc == NST - 1) ? 0 : sc + 1;
        const uint32_t nstA = sb + SM_ST0 + sn * STAGE_BYTES;
        const uint32_t nstB = nstA + A_STAGE_BYTES;

#pragma unroll
        for (int w = 0; w < 4; w++) {
            const int cur = w & 1, nxt = cur ^ 1;

            if (w < 3) {
                // prefetch fragments for k-step w+1 (same stage)
#pragma unroll
                for (int i = 0; i < 4; i++)
                    LDSM_X4(af[nxt][i],
                            stA + aRowByte[i] + ((uint32_t)((2 * (w + 1) + hbA) ^ aR7[i]) << 4));
#pragma unroll
                for (int j = 0; j < 4; j++)
                    LDSM_X4(bf[nxt][j],
                            stB + bRowByte[j] + ((uint32_t)((2 * (w + 1) + hbB) ^ bR7[j]) << 4));
            } else {
                // stage boundary: next stage is ready (wait), sync, prefetch its w=0
                cp_wait<1>();
                __syncthreads();
                if (kt + 1 < KITERS) {
#pragma unroll
                    for (int i = 0; i < 4; i++)
                        LDSM_X4(af[nxt][i],
                                nstA + aRowByte[i] + ((uint32_t)(hbA ^ aR7[i]) << 4));
#pragma unroll
                    for (int j = 0; j < 4; j++)
                        LDSM_X4(bf[nxt][j],
                                nstB + bRowByte[j] + ((uint32_t)(hbB ^ bR7[j]) << 4));
                }
            }

            // MMA burst for k-step w (fragments already in registers)
#pragma unroll
            for (int i = 0; i < 4; i++)
#pragma unroll
                for (int j = 0; j < 4; j++) {
                    mma16816(acc[i][2 * j],     af[cur][i], bf[cur][j][0], bf[cur][j][1]);
                    mma16816(acc[i][2 * j + 1], af[cur][i], bf[cur][j][2], bf[cur][j][3]);
                }
        }

        sc = sn;
        si = (si == NST - 1) ? 0 : si + 1;
    }

    // ---- epilogue ----
    const int r4 = lid >> 2, c4 = lid & 3;
#pragma unroll
    for (int i = 0; i < 4; i++) {
        const int row = m0 + wm * 64 + i * 16 + r4;
        float* o0 = out + (size_t)row * N_DIM + n0;
        float* o1 = out + (size_t)(row + 8) * N_DIM + n0;
#pragma unroll
        for (int j = 0; j < 8; j++) {
            const int col = wn * 64 + j * 8 + c4 * 2;
            const float b0 = bias_sm[col], b1 = bias_sm[col + 1];
            float2 v0 = make_float2(acc[i][j][0] + b0, acc[i][j][1] + b1);
            float2 v1 = make_float2(acc[i][j][2] + b0, acc[i][j][3] + b1);
            *reinterpret_cast<float2*>(o0 + col) = v0;
            *reinterpret_cast<float2*>(o1 + col) = v1;
        }
    }
}

// ============================================================
// Host side
// ============================================================
extern "C" void kernel_launch(void* const* d_in, const int* in_sizes, int n_in,
                              void* d_out, int out_size) {
    const float* x    = (const float*)d_in[0];
    const float* w    = (const float*)d_in[1];
    const float* bias = (const float*)d_in[2];
    float* out        = (float*)d_out;

    void *p_ah = nullptr, *p_bt = nullptr;
    cudaGetSymbolAddress(&p_ah, g_Ah);
    cudaGetSymbolAddress(&p_bt, g_Bt);

    const int n4 = (B_DIM * K_DIM) / 4;
    prep_x_kernel<<<(n4 + 255) / 256, 256>>>((const float4*)x, (uint2*)p_ah, n4);
    prep_bt_kernel<<<dim3(N_DIM / 32, K_DIM / 32), dim3(32, 8)>>>(w, (__half*)p_bt);

    static bool attr_set = false;
    if (!attr_set) {
        cudaFuncSetAttribute(binary_dense_gemm,
                             cudaFuncAttributeMaxDynamicSharedMemorySize, SMEM_BYTES);
        attr_set = true;
    }
    const int grid = (B_DIM / BM) * (N_DIM / BN);   // 1024
    binary_dense_gemm<<<grid, 256, SMEM_BYTES>>>(
        (const __half*)p_ah, (const __half*)p_bt, bias, out);
}

// round 6
// speedup vs baseline: 1.7586x; 1.0294x over previous
#include <cuda_runtime.h>
#include <cuda.h>
#include <cuda_fp16.h>
#include <cstdint>

// ============================================================
// Problem sizes
// ============================================================
#define B_DIM 8192
#define K_DIM 4096
#define N_DIM 4096

// GEMM tiling
#define BM 128
#define BN 256
#define BK 128                 // per stage; stage = two 64-half sub-stages
#define NST 2
#define KITERS (K_DIM / BK)    // 32

#define A_HALF 16384           // 128 rows * 128B (64 halfs of k)
#define B_HALF 32768           // 256 rows * 128B
#define STAGE_BYTES (2 * (A_HALF + B_HALF))   // 98304

#define SM_ST0      1024                      // bias in [0,1024)
#define SMEM_BYTES  (SM_ST0 + NST * STAGE_BYTES)   // 197632

// ============================================================
// Device-global scratch
// ============================================================
__device__ __half g_Ah[(size_t)B_DIM * K_DIM];   // 64 MB  x as fp16
__device__ __half g_Bt[(size_t)N_DIM * K_DIM];   // 32 MB  sign(W)^T, K-major

// ============================================================
// Asm helpers
// ============================================================
__device__ __forceinline__ uint32_t smem_u32(const void* p) {
    uint32_t a;
    asm("{ .reg .u64 t; cvta.to.shared.u64 t, %1; cvt.u32.u64 %0, t; }" : "=r"(a) : "l"(p));
    return a;
}

__device__ __forceinline__ void cp_async16(uint32_t saddr, const void* gaddr) {
    asm volatile("cp.async.cg.shared.global [%0], [%1], 16;" :: "r"(saddr), "l"(gaddr));
}
#define CP_COMMIT() asm volatile("cp.async.commit_group;" ::: "memory")
template <int N>
__device__ __forceinline__ void cp_wait() {
    asm volatile("cp.async.wait_group %0;" :: "n"(N) : "memory");
}

#define LDSM_X4(d, addr) \
    asm volatile("ldmatrix.sync.aligned.m8n8.x4.shared.b16 {%0,%1,%2,%3}, [%4];" \
        : "=r"((d)[0]), "=r"((d)[1]), "=r"((d)[2]), "=r"((d)[3]) : "r"(addr))

__device__ __forceinline__ void mma16816(float* d,
                                         const uint32_t* a, uint32_t b0, uint32_t b1) {
    asm volatile(
        "mma.sync.aligned.m16n8k16.row.col.f32.f16.f16.f32 "
        "{%0,%1,%2,%3}, {%4,%5,%6,%7}, {%8,%9}, {%0,%1,%2,%3};"
        : "+f"(d[0]), "+f"(d[1]), "+f"(d[2]), "+f"(d[3])
        : "r"(a[0]), "r"(a[1]), "r"(a[2]), "r"(a[3]), "r"(b0), "r"(b1));
}

// ============================================================
// Prep 1: x fp32 -> fp16 (2 independent float4 per thread for MLP)
// ============================================================
__global__ void __launch_bounds__(256)
prep_x_kernel(const float4* __restrict__ x, uint2* __restrict__ xh, int n4) {
    int i0 = (blockIdx.x * blockDim.x + threadIdx.x) * 2;
    if (i0 + 1 >= n4) {
        if (i0 < n4) {
            float4 v = x[i0];
            __half2 lo = __floats2half2_rn(v.x, v.y);
            __half2 hi = __floats2half2_rn(v.z, v.w);
            uint2 o;
            o.x = *reinterpret_cast<uint32_t*>(&lo);
            o.y = *reinterpret_cast<uint32_t*>(&hi);
            xh[i0] = o;
        }
        return;
    }
    float4 v0 = x[i0];
    float4 v1 = x[i0 + 1];
    __half2 a0 = __floats2half2_rn(v0.x, v0.y);
    __half2 a1 = __floats2half2_rn(v0.z, v0.w);
    __half2 b0 = __floats2half2_rn(v1.x, v1.y);
    __half2 b1 = __floats2half2_rn(v1.z, v1.w);
    uint2 o0, o1;
    o0.x = *reinterpret_cast<uint32_t*>(&a0);
    o0.y = *reinterpret_cast<uint32_t*>(&a1);
    o1.x = *reinterpret_cast<uint32_t*>(&b0);
    o1.y = *reinterpret_cast<uint32_t*>(&b1);
    xh[i0] = o0;
    xh[i0 + 1] = o1;
}

// ============================================================
// Prep 2: Bt[n][k] = sign(W[k][n]) as fp16 (tiled transpose)
// ============================================================
__global__ void __launch_bounds__(256)
prep_bt_kernel(const float* __restrict__ w, __half* __restrict__ bt) {
    __shared__ float tile[32][33];
    const int n_base = blockIdx.x * 32;
    const int k_base = blockIdx.y * 32;
#pragma unroll
    for (int i = 0; i < 32; i += 8) {
        tile[threadIdx.y + i][threadIdx.x] =
            w[(size_t)(k_base + threadIdx.y + i) * N_DIM + n_base + threadIdx.x];
    }
    __syncthreads();
#pragma unroll
    for (int i = 0; i < 32; i += 8) {
        float v = tile[threadIdx.x][threadIdx.y + i];
        float s = (v > 0.f) ? 1.f : ((v < 0.f) ? -1.f : 0.f);
        bt[(size_t)(n_base + threadIdx.y + i) * K_DIM + k_base + threadIdx.x] = __float2half_rn(s);
    }
}

// ============================================================
// Main GEMM: 256 threads = 8 warps (2x4), warp tile 64x64
// BK=128 (two 64-half sub-stages), NST=2, ldmatrix.x4,
// register-double-buffered fragments
// ============================================================
__global__ void __launch_bounds__(256, 1)
binary_dense_gemm(const __half* __restrict__ Ah,
                  const __half* __restrict__ Bt,
                  const float* __restrict__ bias,
                  float* __restrict__ out) {
    extern __shared__ char smem_raw[];
    float* bias_sm = reinterpret_cast<float*>(smem_raw);
    const uint32_t sb = smem_u32(smem_raw);

    const int tid = threadIdx.x;
    const int wid = tid >> 5;
    const int lid = tid & 31;
    const int wm = wid >> 2;        // 0..1
    const int wn = wid & 3;         // 0..3

    // ---- tile rasterization: supergroups of 8 m-tiles x 16 n-tiles ----
    const int bid = blockIdx.x;
    const int gid = bid >> 7;
    const int rem = bid & 127;
    const int mt  = gid * 8 + (rem & 7);
    const int nt  = rem >> 3;
    const int m0  = mt * BM;
    const int n0  = nt * BN;

    bias_sm[tid] = bias[n0 + tid];

    // ---- cp.async mapping (per 64-half sub-stage): A 4 chunks, B 8 chunks ----
    uint32_t aOff[4]; int aGI[4];
#pragma unroll
    for (int i = 0; i < 4; i++) {
        int c = tid + i * 256, r = c >> 3, ch = c & 7;
        aOff[i] = r * 128 + ((ch ^ (r & 7)) << 4);
        aGI[i]  = r * K_DIM + ch * 8;
    }
    uint32_t bOff[8]; int bGI[8];
#pragma unroll
    for (int i = 0; i < 8; i++) {
        int c = tid + i * 256, r = c >> 3, ch = c & 7;
        bOff[i] = r * 128 + ((ch ^ (r & 7)) << 4);
        bGI[i]  = r * K_DIM + ch * 8;
    }

    const __half* gA = Ah + (size_t)m0 * K_DIM;
    const __half* gB = Bt + (size_t)n0 * K_DIM;

    auto issue_stage = [&](int slot, int kt) {
        const uint32_t st = sb + SM_ST0 + slot * STAGE_BYTES;
        const int k0 = kt * BK;
#pragma unroll
        for (int h = 0; h < 2; h++)
#pragma unroll
            for (int i = 0; i < 4; i++)
                cp_async16(st + h * A_HALF + aOff[i], gA + aGI[i] + k0 + h * 64);
#pragma unroll
        for (int h = 0; h < 2; h++)
#pragma unroll
            for (int i = 0; i < 8; i++)
                cp_async16(st + 2 * A_HALF + h * B_HALF + bOff[i], gB + bGI[i] + k0 + h * 64);
    };

    // ---- ldmatrix lane addressing ----
    const int hbA = lid >> 4;
    uint32_t aRowByte[4], aR7[4];
#pragma unroll
    for (int i = 0; i < 4; i++) {
        int r = wm * 64 + i * 16 + (lid & 15);
        aRowByte[i] = r * 128;
        aR7[i] = r & 7;
    }
    const int hbB = (lid >> 3) & 1;
    uint32_t bRowByte[4], bR7[4];
#pragma unroll
    for (int j = 0; j < 4; j++) {
        int r = wn * 64 + j * 16 + ((lid >> 4) << 3) + (lid & 7);
        bRowByte[j] = r * 128;
        bR7[j] = r & 7;
    }

    float acc[4][8][4];
#pragma unroll
    for (int i = 0; i < 4; i++)
#pragma unroll
        for (int j = 0; j < 8; j++)
#pragma unroll
            for (int q = 0; q < 4; q++) acc[i][j][q] = 0.f;

    uint32_t af[2][4][4], bf[2][4][4];

    // ---- prologue: stage 0, then first fragments ----
    issue_stage(0, 0); CP_COMMIT();
    cp_wait<0>();
    __syncthreads();
    {
        const uint32_t stA = sb + SM_ST0;
        const uint32_t stB = stA + 2 * A_HALF;
#pragma unroll
        for (int i = 0; i < 4; i++)
            LDSM_X4(af[0][i], stA + aRowByte[i] + ((uint32_t)(hbA ^ aR7[i]) << 4));
#pragma unroll
        for (int j = 0; j < 4; j++)
            LDSM_X4(bf[0][j], stB + bRowByte[j] + ((uint32_t)(hbB ^ bR7[j]) << 4));
    }

    for (int kt = 0; kt < KITERS; kt++) {
        // issue next stage into the slot freed by kt-1 (ordered by kt-1's w7 sync)
        if (kt + 1 < KITERS) issue_stage((kt + 1) & 1, kt + 1);
        CP_COMMIT();

        const uint32_t stA = sb + SM_ST0 + (kt & 1) * STAGE_BYTES;
        const uint32_t stB = stA + 2 * A_HALF;
        const uint32_t nstA = sb + SM_ST0 + ((kt + 1) & 1) * STAGE_BYTES;
        const uint32_t nstB = nstA + 2 * A_HALF;

#pragma unroll
        for (int w = 0; w < 8; w++) {          // eight k16 steps per BK=128
            const int cur = w & 1, nxt = cur ^ 1;

            if (w < 7) {
                // prefetch fragments for k-step w+1 (same stage)
                const int h2  = (w + 1) >> 2;
                const int wk2 = (w + 1) & 3;
                const uint32_t bA = stA + h2 * A_HALF;
                const uint32_t bB = stB + h2 * B_HALF;
#pragma unroll
                for (int i = 0; i < 4; i++)
                    LDSM_X4(af[nxt][i],
                            bA + aRowByte[i] + ((uint32_t)((2 * wk2 + hbA) ^ aR7[i]) << 4));
#pragma unroll
                for (int j = 0; j < 4; j++)
                    LDSM_X4(bf[nxt][j],
                            bB + bRowByte[j] + ((uint32_t)((2 * wk2 + hbB) ^ bR7[j]) << 4));
            } else {
                // stage boundary: wait next stage, sync, prefetch its w=0
                cp_wait<0>();
                __syncthreads();
                if (kt + 1 < KITERS) {
#pragma unroll
                    for (int i = 0; i < 4; i++)
                        LDSM_X4(af[nxt][i],
                                nstA + aRowByte[i] + ((uint32_t)(hbA ^ aR7[i]) << 4));
#pragma unroll
                    for (int j = 0; j < 4; j++)
                        LDSM_X4(bf[nxt][j],
                                nstB + bRowByte[j] + ((uint32_t)(hbB ^ bR7[j]) << 4));
                }
            }

            // MMA burst for k-step w (fragments already in registers)
            const int h  = w >> 2;
            (void)h;
#pragma unroll
            for (int i = 0; i < 4; i++)
#pragma unroll
                for (int j = 0; j < 4; j++) {
                    mma16816(acc[i][2 * j],     af[cur][i], bf[cur][j][0], bf[cur][j][1]);
                    mma16816(acc[i][2 * j + 1], af[cur][i], bf[cur][j][2], bf[cur][j][3]);
                }
        }
    }

    // ---- epilogue ----
    const int r4 = lid >> 2, c4 = lid & 3;
#pragma unroll
    for (int i = 0; i < 4; i++) {
        const int row = m0 + wm * 64 + i * 16 + r4;
        float* o0 = out + (size_t)row * N_DIM + n0;
        float* o1 = out + (size_t)(row + 8) * N_DIM + n0;
#pragma unroll
        for (int j = 0; j < 8; j++) {
            const int col = wn * 64 + j * 8 + c4 * 2;
            const float b0 = bias_sm[col], b1 = bias_sm[col + 1];
            float2 v0 = make_float2(acc[i][j][0] + b0, acc[i][j][1] + b1);
            float2 v1 = make_float2(acc[i][j][2] + b0, acc[i][j][3] + b1);
            *reinterpret_cast<float2*>(o0 + col) = v0;
            *reinterpret_cast<float2*>(o1 + col) = v1;
        }
    }
}

// ============================================================
// Host side
// ============================================================
extern "C" void kernel_launch(void* const* d_in, const int* in_sizes, int n_in,
                              void* d_out, int out_size) {
    const float* x    = (const float*)d_in[0];
    const float* w    = (const float*)d_in[1];
    const float* bias = (const float*)d_in[2];
    float* out        = (float*)d_out;

    void *p_ah = nullptr, *p_bt = nullptr;
    cudaGetSymbolAddress(&p_ah, g_Ah);
    cudaGetSymbolAddress(&p_bt, g_Bt);

    const int n4 = (B_DIM * K_DIM) / 4;
    prep_x_kernel<<<(n4 / 2 + 255) / 256, 256>>>((const float4*)x, (uint2*)p_ah, n4);
    prep_bt_kernel<<<dim3(N_DIM / 32, K_DIM / 32), dim3(32, 8)>>>(w, (__half*)p_bt);

    static bool attr_set = false;
    if (!attr_set) {
        cudaFuncSetAttribute(binary_dense_gemm,
                             cudaFuncAttributeMaxDynamicSharedMemorySize, SMEM_BYTES);
        attr_set = true;
    }
    const int grid = (B_DIM / BM) * (N_DIM / BN);   // 1024
    binary_dense_gemm<<<grid, 256, SMEM_BYTES>>>(
        (const __half*)p_ah, (const __half*)p_bt, bias, out);
}